// round 7
// baseline (speedup 1.0000x reference)
#include <cuda_runtime.h>
#include <cuda_bf16.h>
#include <cstdint>
#include <cmath>

#define NROWS 8192
#define DDIM  64
#define NCLS  100
#define EPSV  1e-6f

#define TB   128                // threads per block (4 warps), 1 row/thread
#define TILE 128                // tile edge: 128 i-rows x 128 j-rows
#define NB   (NROWS / TILE)     // 64 row-blocks
#define NTILES (NB * (NB + 1) / 2)   // 2080 upper-tri tiles
#define FBLOCKS 64

// Scratch (device globals; no allocation allowed).
// Layout [slot][row]: coalesced STG from main, coalesced LDG in final1.
// Every slot has exactly ONE writer per replay -> deterministic, no atomics.
__device__ float g_srow [NB * NROWS];
__device__ float g_snrow[NB * NROWS];
__device__ int   g_cnt[NCLS];
__device__ float g_part[FBLOCKS];

static __device__ __forceinline__ unsigned long long fadd2(unsigned long long a,
                                                           unsigned long long b) {
    unsigned long long r;
    asm("add.rn.f32x2 %0, %1, %2;" : "=l"(r) : "l"(a), "l"(b));
    return r;
}

static __device__ __forceinline__ float frcp(float x) {
    float r;
    asm("rcp.approx.f32 %0, %1;" : "=f"(r) : "f"(x));
    return r;
}

__global__ void __launch_bounds__(TB, 5)
ecstfl_main_kernel(const float* __restrict__ X, const int* __restrict__ lab) {
    __shared__ float shx[TILE * DDIM];                 // -x_j/2 tile (32 KB)
    __shared__ int   shl[TILE];
    __shared__ unsigned long long cpn[4][TILE];        // per-warp packed col partials

    // Decode upper-triangular tile (bi <= bj) from linear block index.
    const int t = blockIdx.x;
    int bi = (int)(64.5f - sqrtf(64.5f * 64.5f - 2.0f * (float)t));
    while (bi > 0 && bi * NB - bi * (bi - 1) / 2 > t) bi--;
    while ((bi + 1) * NB - (bi + 1) * bi / 2 <= t) bi++;
    const int bj = bi + (t - (bi * NB - bi * (bi - 1) / 2));
    const bool diag = (bi == bj);

    const int tid  = threadIdx.x;
    const int w    = tid >> 5;
    const int lane = tid & 31;
    const int i    = bi * TILE + tid;      // owned row
    const int J0   = bj * TILE;

    // My row x_i in registers (raw scale), 64 floats.
    float xi[DDIM];
    {
        const float4* r4 = (const float4*)(X + (size_t)i * DDIM);
        #pragma unroll
        for (int q = 0; q < DDIM / 4; q++) {
            float4 v = r4[q];
            xi[4*q] = v.x; xi[4*q+1] = v.y; xi[4*q+2] = v.z; xi[4*q+3] = v.w;
        }
    }
    const int myl = lab[i];

    // Stage J tile as -x_j/2 (power-of-2 exact): 16 float4 per thread.
    {
        const float4* src = (const float4*)(X + (size_t)J0 * DDIM);
        float4* dst = (float4*)shx;
        #pragma unroll
        for (int r = 0; r < (TILE * DDIM / 4) / TB; r++) {
            float4 v = src[tid + r * TB];
            v.x *= -0.5f; v.y *= -0.5f; v.z *= -0.5f; v.w *= -0.5f;
            dst[tid + r * TB] = v;
        }
        shl[tid] = lab[J0 + tid];
    }
    __syncthreads();

    float sp = 0.0f, sn = 0.0f;

    #pragma unroll 1
    for (int jl = 0; jl < TILE; jl++) {
        const float4* row = (const float4*)(shx + jl * DDIM);
        // 4 independent FFMA-imm accumulator chains (dep distance 8 >= lat 4).
        float a0 = 0.0f, a1 = 0.0f, a2 = 0.0f, a3 = 0.0f;
        #pragma unroll
        for (int q = 0; q < 16; q++) {
            float4 v = row[q];                          // LDS.128 broadcast
            // d = x_i*0.5 + (-x_j/2)  -> FFMA-imm (rt1)
            // a = |d|*2.0 + a         -> FFMA-imm (rt1), |.| folded as src-mod
            float d0 = fmaf(xi[4*q+0], 0.5f, v.x);
            float d1 = fmaf(xi[4*q+1], 0.5f, v.y);
            float d2 = fmaf(xi[4*q+2], 0.5f, v.z);
            float d3 = fmaf(xi[4*q+3], 0.5f, v.w);
            a0 = fmaf(fabsf(d0), 2.0f, a0);
            a1 = fmaf(fabsf(d1), 2.0f, a1);
            a2 = fmaf(fabsf(d2), 2.0f, a2);
            a3 = fmaf(fabsf(d3), 2.0f, a3);
        }
        float dist = (a0 + a1) + (a2 + a3);

        float r  = frcp(dist + EPSV);
        bool  m  = (shl[jl] == myl);
        float csp = m ? dist : 0.0f;
        float csn = m ? 0.0f : r;
        sp += csp;
        sn += csn;

        if (!diag) {
            // Symmetric credit: packed butterfly over the 32 lanes (32 i's).
            unsigned long long pv;
            asm("mov.b64 %0, {%1, %2};" : "=l"(pv) : "f"(csp), "f"(csn));
            #pragma unroll
            for (int o = 16; o > 0; o >>= 1) {
                unsigned long long qv = __shfl_xor_sync(0xFFFFFFFFu, pv, o);
                pv = fadd2(pv, qv);
            }
            if (lane == 0) cpn[w][jl] = pv;
        }
    }

    // Row part: unique slot [bj][i] (coalesced STG).
    g_srow [bj * NROWS + i] = sp;
    g_snrow[bj * NROWS + i] = sn;

    if (!diag) {
        __syncthreads();
        // Merge 4 warp partials per column (fixed order), transposed slot.
        unsigned long long pv = fadd2(fadd2(cpn[0][tid], cpn[1][tid]),
                                      fadd2(cpn[2][tid], cpn[3][tid]));
        float csp, csn;
        asm("mov.b64 {%0, %1}, %2;" : "=f"(csp), "=f"(csn) : "l"(pv));
        const int j = J0 + tid;
        g_srow [bi * NROWS + j] = csp;
        g_snrow[bi * NROWS + j] = csn;
    }
}

__global__ void ecstfl_cntzero_kernel() {
    if (threadIdx.x < NCLS) g_cnt[threadIdx.x] = 0;
}

__global__ void ecstfl_count_kernel(const int* __restrict__ lab) {
    int t = blockIdx.x * blockDim.x + threadIdx.x;
    if (t < NROWS) atomicAdd(&g_cnt[lab[t]], 1);   // int atomics: order-invariant
}

// Position-3 filler (also zeroes g_part) so main lands at captured slot 4.
__global__ void ecstfl_partzero_kernel() {
    if (threadIdx.x < FBLOCKS) g_part[threadIdx.x] = 0.0f;
}

// Finalize stage 1: 64 blocks x 128 threads; [slot][row] layout -> coalesced.
__global__ void __launch_bounds__(128)
ecstfl_final1_kernel(const int* __restrict__ lab) {
    __shared__ float red[128];
    const int i = blockIdx.x * 128 + threadIdx.x;

    float sp = 0.0f, sn = 0.0f;
    #pragma unroll
    for (int c = 0; c < NB; c++) {             // fixed order -> deterministic
        sp += g_srow [c * NROWS + i];
        sn += g_snrow[c * NROWS + i];
    }
    float cp  = (float)g_cnt[lab[i]];          // same-label count incl. self
    float att = sp / (cp + EPSV);              // (cnt-1)+1+eps == cnt+eps
    float rep = sn / ((float)NROWS - cp + 1.0f + EPSV);
    red[threadIdx.x] = att * rep;
    __syncthreads();
    #pragma unroll
    for (int o = 64; o > 0; o >>= 1) {
        if (threadIdx.x < o) red[threadIdx.x] += red[threadIdx.x + o];
        __syncthreads();
    }
    if (threadIdx.x == 0) g_part[blockIdx.x] = red[0];
}

__global__ void ecstfl_final2_kernel(float* __restrict__ out) {
    __shared__ float red[FBLOCKS];
    red[threadIdx.x] = g_part[threadIdx.x];
    __syncthreads();
    #pragma unroll
    for (int o = FBLOCKS / 2; o > 0; o >>= 1) {
        if (threadIdx.x < o) red[threadIdx.x] += red[threadIdx.x + o];
        __syncthreads();
    }
    if (threadIdx.x == 0)
        out[0] = red[0] / ((float)NROWS * (float)NROWS);   // mean(att*rep/N)
}

extern "C" void kernel_launch(void* const* d_in, const int* in_sizes, int n_in,
                              void* d_out, int out_size) {
    (void)in_sizes; (void)n_in; (void)out_size;
    const float* X   = (const float*)d_in[0];
    const int*   lab = (const int*)d_in[1];
    float* out = (float*)d_out;

    ecstfl_cntzero_kernel<<<1, 128>>>();                       // pos 1
    ecstfl_count_kernel<<<(NROWS + 255) / 256, 256>>>(lab);    // pos 2
    ecstfl_partzero_kernel<<<1, 64>>>();                       // pos 3 (filler)
    ecstfl_main_kernel<<<NTILES, TB>>>(X, lab);                // pos 4 <- profiled
    ecstfl_final1_kernel<<<FBLOCKS, 128>>>(lab);               // pos 5
    ecstfl_final2_kernel<<<1, FBLOCKS>>>(out);                 // pos 6
}

// round 8
// speedup vs baseline: 1.0706x; 1.0706x over previous
#include <cuda_runtime.h>
#include <cuda_bf16.h>
#include <cstdint>
#include <cmath>

#define NROWS 8192
#define DDIM  64
#define NCLS  100
#define EPSV  1e-6f

#define TB   64                 // threads per block (2 warps), 2 rows/thread
#define TILE 128                // tile edge: 128 i-rows x 128 j-rows
#define NB   (NROWS / TILE)     // 64 row-blocks
#define NTILES (NB * (NB + 1) / 2)   // 2080 upper-tri tiles
#define FBLOCKS 64

// Scratch (device globals; no allocation allowed).
// Layout [slot][row]: coalesced STG from main, coalesced LDG in final1.
// Every slot has exactly ONE writer per replay -> deterministic, no atomics.
__device__ float g_srow [NB * NROWS];
__device__ float g_snrow[NB * NROWS];
__device__ int   g_cnt[NCLS];
__device__ float g_part[FBLOCKS];

static __device__ __forceinline__ unsigned long long fadd2(unsigned long long a,
                                                           unsigned long long b) {
    unsigned long long r;
    asm("add.rn.f32x2 %0, %1, %2;" : "=l"(r) : "l"(a), "l"(b));
    return r;
}

static __device__ __forceinline__ float frcp(float x) {
    float r;
    asm("rcp.approx.f32 %0, %1;" : "=f"(r) : "f"(x));
    return r;
}

__global__ void __launch_bounds__(TB, 5)
ecstfl_main_kernel(const float* __restrict__ X, const int* __restrict__ lab) {
    __shared__ float shx[TILE * DDIM];              // -x_j/2 tile (32 KB)
    __shared__ int   shl[TILE];
    // Truncated-butterfly partials: [warp][jl][residue 0..3], packed (sp,sn).
    __shared__ unsigned long long cpn[2][TILE][4];  // 8 KB

    // Decode upper-triangular tile (bi <= bj) from linear block index.
    const int t = blockIdx.x;
    int bi = (int)(64.5f - sqrtf(64.5f * 64.5f - 2.0f * (float)t));
    while (bi > 0 && bi * NB - bi * (bi - 1) / 2 > t) bi--;
    while ((bi + 1) * NB - (bi + 1) * bi / 2 <= t) bi++;
    const int bj = bi + (t - (bi * NB - bi * (bi - 1) / 2));
    const bool diag = (bi == bj);

    const int tid  = threadIdx.x;
    const int w    = tid >> 5;
    const int lane = tid & 31;
    const int i0   = bi * TILE + tid;      // first owned row
    const int i1   = i0 + TB;              // second owned row
    const int J0   = bj * TILE;

    // Two rows of x_i in registers (raw scale).
    float xiA[DDIM], xiB[DDIM];
    {
        const float4* ra = (const float4*)(X + (size_t)i0 * DDIM);
        const float4* rb = (const float4*)(X + (size_t)i1 * DDIM);
        #pragma unroll
        for (int q = 0; q < DDIM / 4; q++) {
            float4 va = ra[q];
            xiA[4*q] = va.x; xiA[4*q+1] = va.y; xiA[4*q+2] = va.z; xiA[4*q+3] = va.w;
            float4 vb = rb[q];
            xiB[4*q] = vb.x; xiB[4*q+1] = vb.y; xiB[4*q+2] = vb.z; xiB[4*q+3] = vb.w;
        }
    }
    const int lA = lab[i0];
    const int lB = lab[i1];

    // Stage J tile as -x_j/2 (power-of-2 exact): 32 float4 per thread.
    {
        const float4* src = (const float4*)(X + (size_t)J0 * DDIM);
        float4* dst = (float4*)shx;
        #pragma unroll
        for (int r = 0; r < (TILE * DDIM / 4) / TB; r++) {
            float4 v = src[tid + r * TB];
            v.x *= -0.5f; v.y *= -0.5f; v.z *= -0.5f; v.w *= -0.5f;
            dst[tid + r * TB] = v;
        }
        shl[tid]      = lab[J0 + tid];
        shl[tid + TB] = lab[J0 + tid + TB];
    }
    __syncthreads();

    float spA = 0.0f, snA = 0.0f, spB = 0.0f, snB = 0.0f;

    #pragma unroll 1
    for (int jl = 0; jl < TILE; jl++) {
        const float4* row = (const float4*)(shx + jl * DDIM);
        // 8 independent FFMA-imm chains: each touched once per q (dep dist 16).
        float aA0 = 0.0f, aA1 = 0.0f, aA2 = 0.0f, aA3 = 0.0f;
        float aB0 = 0.0f, aB1 = 0.0f, aB2 = 0.0f, aB3 = 0.0f;
        #pragma unroll
        for (int q = 0; q < 16; q++) {
            float4 v = row[q];                          // LDS.128 broadcast
            // d = x_i*0.5 + (-x_j/2) -> FFMA-imm (rt1)
            // a = |d|*2.0 + a        -> FFMA-imm (rt1), |.| folded as src-mod
            float dA0 = fmaf(xiA[4*q+0], 0.5f, v.x);
            float dA1 = fmaf(xiA[4*q+1], 0.5f, v.y);
            float dA2 = fmaf(xiA[4*q+2], 0.5f, v.z);
            float dA3 = fmaf(xiA[4*q+3], 0.5f, v.w);
            float dB0 = fmaf(xiB[4*q+0], 0.5f, v.x);
            float dB1 = fmaf(xiB[4*q+1], 0.5f, v.y);
            float dB2 = fmaf(xiB[4*q+2], 0.5f, v.z);
            float dB3 = fmaf(xiB[4*q+3], 0.5f, v.w);
            aA0 = fmaf(fabsf(dA0), 2.0f, aA0);
            aA1 = fmaf(fabsf(dA1), 2.0f, aA1);
            aA2 = fmaf(fabsf(dA2), 2.0f, aA2);
            aA3 = fmaf(fabsf(dA3), 2.0f, aA3);
            aB0 = fmaf(fabsf(dB0), 2.0f, aB0);
            aB1 = fmaf(fabsf(dB1), 2.0f, aB1);
            aB2 = fmaf(fabsf(dB2), 2.0f, aB2);
            aB3 = fmaf(fabsf(dB3), 2.0f, aB3);
        }
        float distA = (aA0 + aA1) + (aA2 + aA3);
        float distB = (aB0 + aB1) + (aB2 + aB3);

        float rA = frcp(distA + EPSV);
        float rB = frcp(distB + EPSV);
        int   jlab = shl[jl];
        bool  mA = (jlab == lA);
        bool  mB = (jlab == lB);
        float cspA = mA ? distA : 0.0f;
        float csnA = mA ? 0.0f  : rA;
        float cspB = mB ? distB : 0.0f;
        float csnB = mB ? 0.0f  : rB;
        spA += cspA;  snA += csnA;
        spB += cspB;  snB += csnB;

        if (!diag) {
            // Truncated butterfly (3 steps): lanes 0..3 hold 8-lane partials.
            float bsp = cspA + cspB;
            float bsn = csnA + csnB;
            unsigned long long pv;
            asm("mov.b64 %0, {%1, %2};" : "=l"(pv) : "f"(bsp), "f"(bsn));
            #pragma unroll
            for (int o = 16; o >= 4; o >>= 1) {
                unsigned long long qv = __shfl_xor_sync(0xFFFFFFFFu, pv, o);
                pv = fadd2(pv, qv);
            }
            if (lane < 4) cpn[w][jl][lane] = pv;
        }
    }

    // Row parts: unique slots [bj][i0], [bj][i1] (coalesced STG).
    g_srow [bj * NROWS + i0] = spA;
    g_snrow[bj * NROWS + i0] = snA;
    g_srow [bj * NROWS + i1] = spB;
    g_snrow[bj * NROWS + i1] = snB;

    if (!diag) {
        __syncthreads();
        // Merge 2 warps x 4 residues per column (fixed order), transposed slot.
        #pragma unroll
        for (int h = 0; h < 2; h++) {
            int c = tid + h * TB;
            unsigned long long pv =
                fadd2(fadd2(fadd2(cpn[0][c][0], cpn[0][c][1]),
                            fadd2(cpn[0][c][2], cpn[0][c][3])),
                      fadd2(fadd2(cpn[1][c][0], cpn[1][c][1]),
                            fadd2(cpn[1][c][2], cpn[1][c][3])));
            float csp, csn;
            asm("mov.b64 {%0, %1}, %2;" : "=f"(csp), "=f"(csn) : "l"(pv));
            int j = J0 + c;
            g_srow [bi * NROWS + j] = csp;
            g_snrow[bi * NROWS + j] = csn;
        }
    }
}

__global__ void ecstfl_cntzero_kernel() {
    if (threadIdx.x < NCLS) g_cnt[threadIdx.x] = 0;
}

__global__ void ecstfl_count_kernel(const int* __restrict__ lab) {
    int t = blockIdx.x * blockDim.x + threadIdx.x;
    if (t < NROWS) atomicAdd(&g_cnt[lab[t]], 1);   // int atomics: order-invariant
}

// Position-3 filler (also zeroes g_part) so main lands at captured slot 4.
__global__ void ecstfl_partzero_kernel() {
    if (threadIdx.x < FBLOCKS) g_part[threadIdx.x] = 0.0f;
}

// Finalize stage 1: 64 blocks x 128 threads; [slot][row] layout -> coalesced.
__global__ void __launch_bounds__(128)
ecstfl_final1_kernel(const int* __restrict__ lab) {
    __shared__ float red[128];
    const int i = blockIdx.x * 128 + threadIdx.x;

    float sp = 0.0f, sn = 0.0f;
    #pragma unroll
    for (int c = 0; c < NB; c++) {             // fixed order -> deterministic
        sp += g_srow [c * NROWS + i];
        sn += g_snrow[c * NROWS + i];
    }
    float cp  = (float)g_cnt[lab[i]];          // same-label count incl. self
    float att = sp / (cp + EPSV);              // (cnt-1)+1+eps == cnt+eps
    float rep = sn / ((float)NROWS - cp + 1.0f + EPSV);
    red[threadIdx.x] = att * rep;
    __syncthreads();
    #pragma unroll
    for (int o = 64; o > 0; o >>= 1) {
        if (threadIdx.x < o) red[threadIdx.x] += red[threadIdx.x + o];
        __syncthreads();
    }
    if (threadIdx.x == 0) g_part[blockIdx.x] = red[0];
}

__global__ void ecstfl_final2_kernel(float* __restrict__ out) {
    __shared__ float red[FBLOCKS];
    red[threadIdx.x] = g_part[threadIdx.x];
    __syncthreads();
    #pragma unroll
    for (int o = FBLOCKS / 2; o > 0; o >>= 1) {
        if (threadIdx.x < o) red[threadIdx.x] += red[threadIdx.x + o];
        __syncthreads();
    }
    if (threadIdx.x == 0)
        out[0] = red[0] / ((float)NROWS * (float)NROWS);   // mean(att*rep/N)
}

extern "C" void kernel_launch(void* const* d_in, const int* in_sizes, int n_in,
                              void* d_out, int out_size) {
    (void)in_sizes; (void)n_in; (void)out_size;
    const float* X   = (const float*)d_in[0];
    const int*   lab = (const int*)d_in[1];
    float* out = (float*)d_out;

    ecstfl_cntzero_kernel<<<1, 128>>>();                       // pos 1
    ecstfl_count_kernel<<<(NROWS + 255) / 256, 256>>>(lab);    // pos 2
    ecstfl_partzero_kernel<<<1, 64>>>();                       // pos 3 (filler)
    ecstfl_main_kernel<<<NTILES, TB>>>(X, lab);                // pos 4 <- profiled
    ecstfl_final1_kernel<<<FBLOCKS, 128>>>(lab);               // pos 5
    ecstfl_final2_kernel<<<1, FBLOCKS>>>(out);                 // pos 6
}

// round 9
// speedup vs baseline: 1.1382x; 1.0631x over previous
#include <cuda_runtime.h>
#include <cuda_bf16.h>
#include <cstdint>
#include <cmath>

#define NROWS 8192
#define DDIM  64
#define NCLS  100
#define EPSV  1e-6f

#define TB   64                 // threads per block (2 warps), 2 rows/thread
#define TILE 128                // tile edge: 128 i-rows x 128 j-rows
#define NB   (NROWS / TILE)     // 64 row-blocks
#define NTILES (NB * (NB + 1) / 2)   // 2080 upper-tri tiles
#define FBLOCKS 64

// Scratch (device globals; no allocation allowed).
// Layout [slot][row]: coalesced STG from main, coalesced LDG in final1.
// Every slot has exactly ONE writer per replay -> deterministic, no atomics.
__device__ float g_srow [NB * NROWS];
__device__ float g_snrow[NB * NROWS];
__device__ int   g_cnt[NCLS];
__device__ float g_part[FBLOCKS];

static __device__ __forceinline__ unsigned long long fadd2(unsigned long long a,
                                                           unsigned long long b) {
    unsigned long long r;
    asm("add.rn.f32x2 %0, %1, %2;" : "=l"(r) : "l"(a), "l"(b));
    return r;
}

static __device__ __forceinline__ float frcp(float x) {
    float r;
    asm("rcp.approx.f32 %0, %1;" : "=f"(r) : "f"(x));
    return r;
}

__global__ void __launch_bounds__(TB, 5)
ecstfl_main_kernel(const float* __restrict__ X, const int* __restrict__ lab) {
    __shared__ float shx[TILE * DDIM];              // -x_j/2 tile (32 KB)
    __shared__ int   shl[TILE];
    // Truncated-butterfly partials: [warp][jl][residue 0..3], packed (sp,sn).
    __shared__ unsigned long long cpn[2][TILE][4];  // 8 KB

    // Decode upper-triangular tile (bi <= bj) from linear block index.
    const int t = blockIdx.x;
    int bi = (int)(64.5f - sqrtf(64.5f * 64.5f - 2.0f * (float)t));
    while (bi > 0 && bi * NB - bi * (bi - 1) / 2 > t) bi--;
    while ((bi + 1) * NB - (bi + 1) * bi / 2 <= t) bi++;
    const int bj = bi + (t - (bi * NB - bi * (bi - 1) / 2));
    const bool diag = (bi == bj);

    const int tid  = threadIdx.x;
    const int w    = tid >> 5;
    const int lane = tid & 31;
    const int i0   = bi * TILE + tid;      // first owned row
    const int i1   = i0 + TB;              // second owned row
    const int J0   = bj * TILE;

    // Two rows of x_i in registers (raw scale).
    float xiA[DDIM], xiB[DDIM];
    {
        const float4* ra = (const float4*)(X + (size_t)i0 * DDIM);
        const float4* rb = (const float4*)(X + (size_t)i1 * DDIM);
        #pragma unroll
        for (int q = 0; q < DDIM / 4; q++) {
            float4 va = ra[q];
            xiA[4*q] = va.x; xiA[4*q+1] = va.y; xiA[4*q+2] = va.z; xiA[4*q+3] = va.w;
            float4 vb = rb[q];
            xiB[4*q] = vb.x; xiB[4*q+1] = vb.y; xiB[4*q+2] = vb.z; xiB[4*q+3] = vb.w;
        }
    }
    const int lA = lab[i0];
    const int lB = lab[i1];

    // Stage J tile as -x_j/2 (power-of-2 exact): 32 float4 per thread.
    {
        const float4* src = (const float4*)(X + (size_t)J0 * DDIM);
        float4* dst = (float4*)shx;
        #pragma unroll
        for (int r = 0; r < (TILE * DDIM / 4) / TB; r++) {
            float4 v = src[tid + r * TB];
            v.x *= -0.5f; v.y *= -0.5f; v.z *= -0.5f; v.w *= -0.5f;
            dst[tid + r * TB] = v;
        }
        shl[tid]      = lab[J0 + tid];
        shl[tid + TB] = lab[J0 + tid + TB];
    }
    __syncthreads();

    float spA = 0.0f, snA = 0.0f, spB = 0.0f, snB = 0.0f;

    // Process 2 j-rows per iteration: 2i x 2j register tile.
    #pragma unroll 1
    for (int jl = 0; jl < TILE; jl += 2) {
        const float4* row0 = (const float4*)(shx + jl * DDIM);
        const float4* row1 = (const float4*)(shx + (jl + 1) * DDIM);
        // 8 FFMA-imm accumulator chains, each touched 2x per q (dep dist 8).
        float aA00 = 0.0f, aA01 = 0.0f, aB00 = 0.0f, aB01 = 0.0f;  // j0
        float aA10 = 0.0f, aA11 = 0.0f, aB10 = 0.0f, aB11 = 0.0f;  // j1
        #pragma unroll
        for (int q = 0; q < 16; q++) {
            float4 v0 = row0[q];                    // LDS.128 broadcast
            float4 v1 = row1[q];
            // d = x_i*0.5 + (-x_j/2) -> FFMA-imm (rt1)
            // a = |d|*2.0 + a        -> FFMA-imm (rt1), |.| folded as src-mod
            float dA00 = fmaf(xiA[4*q+0], 0.5f, v0.x);
            float dA01 = fmaf(xiA[4*q+1], 0.5f, v0.y);
            float dB00 = fmaf(xiB[4*q+0], 0.5f, v0.x);
            float dB01 = fmaf(xiB[4*q+1], 0.5f, v0.y);
            float dA10 = fmaf(xiA[4*q+0], 0.5f, v1.x);
            float dA11 = fmaf(xiA[4*q+1], 0.5f, v1.y);
            float dB10 = fmaf(xiB[4*q+0], 0.5f, v1.x);
            float dB11 = fmaf(xiB[4*q+1], 0.5f, v1.y);
            aA00 = fmaf(fabsf(dA00), 2.0f, aA00);
            aA01 = fmaf(fabsf(dA01), 2.0f, aA01);
            aB00 = fmaf(fabsf(dB00), 2.0f, aB00);
            aB01 = fmaf(fabsf(dB01), 2.0f, aB01);
            aA10 = fmaf(fabsf(dA10), 2.0f, aA10);
            aA11 = fmaf(fabsf(dA11), 2.0f, aA11);
            aB10 = fmaf(fabsf(dB10), 2.0f, aB10);
            aB11 = fmaf(fabsf(dB11), 2.0f, aB11);
            float eA00 = fmaf(xiA[4*q+2], 0.5f, v0.z);
            float eA01 = fmaf(xiA[4*q+3], 0.5f, v0.w);
            float eB00 = fmaf(xiB[4*q+2], 0.5f, v0.z);
            float eB01 = fmaf(xiB[4*q+3], 0.5f, v0.w);
            float eA10 = fmaf(xiA[4*q+2], 0.5f, v1.z);
            float eA11 = fmaf(xiA[4*q+3], 0.5f, v1.w);
            float eB10 = fmaf(xiB[4*q+2], 0.5f, v1.z);
            float eB11 = fmaf(xiB[4*q+3], 0.5f, v1.w);
            aA00 = fmaf(fabsf(eA00), 2.0f, aA00);
            aA01 = fmaf(fabsf(eA01), 2.0f, aA01);
            aB00 = fmaf(fabsf(eB00), 2.0f, aB00);
            aB01 = fmaf(fabsf(eB01), 2.0f, aB01);
            aA10 = fmaf(fabsf(eA10), 2.0f, aA10);
            aA11 = fmaf(fabsf(eA11), 2.0f, aA11);
            aB10 = fmaf(fabsf(eB10), 2.0f, aB10);
            aB11 = fmaf(fabsf(eB11), 2.0f, aB11);
        }
        float distA0 = aA00 + aA01;
        float distB0 = aB00 + aB01;
        float distA1 = aA10 + aA11;
        float distB1 = aB10 + aB11;

        // Two independent epilogue chains (j0, j1), interleaved by ptxas.
        float rA0 = frcp(distA0 + EPSV);
        float rB0 = frcp(distB0 + EPSV);
        float rA1 = frcp(distA1 + EPSV);
        float rB1 = frcp(distB1 + EPSV);
        int jlab0 = shl[jl];
        int jlab1 = shl[jl + 1];
        bool mA0 = (jlab0 == lA), mB0 = (jlab0 == lB);
        bool mA1 = (jlab1 == lA), mB1 = (jlab1 == lB);
        float cspA0 = mA0 ? distA0 : 0.0f,  csnA0 = mA0 ? 0.0f : rA0;
        float cspB0 = mB0 ? distB0 : 0.0f,  csnB0 = mB0 ? 0.0f : rB0;
        float cspA1 = mA1 ? distA1 : 0.0f,  csnA1 = mA1 ? 0.0f : rA1;
        float cspB1 = mB1 ? distB1 : 0.0f,  csnB1 = mB1 ? 0.0f : rB1;
        spA += cspA0;  snA += csnA0;  spA += cspA1;  snA += csnA1;
        spB += cspB0;  snB += csnB0;  spB += cspB1;  snB += csnB1;

        if (!diag) {
            // Two truncated butterflies (3 steps each), latencies overlapped.
            unsigned long long pv0, pv1;
            {
                float s0 = cspA0 + cspB0, n0 = csnA0 + csnB0;
                float s1 = cspA1 + cspB1, n1 = csnA1 + csnB1;
                asm("mov.b64 %0, {%1, %2};" : "=l"(pv0) : "f"(s0), "f"(n0));
                asm("mov.b64 %0, {%1, %2};" : "=l"(pv1) : "f"(s1), "f"(n1));
            }
            #pragma unroll
            for (int o = 16; o >= 4; o >>= 1) {
                unsigned long long q0 = __shfl_xor_sync(0xFFFFFFFFu, pv0, o);
                unsigned long long q1 = __shfl_xor_sync(0xFFFFFFFFu, pv1, o);
                pv0 = fadd2(pv0, q0);
                pv1 = fadd2(pv1, q1);
            }
            if (lane < 4) {
                cpn[w][jl][lane]     = pv0;
                cpn[w][jl + 1][lane] = pv1;
            }
        }
    }

    // Row parts: unique slots [bj][i0], [bj][i1] (coalesced STG).
    g_srow [bj * NROWS + i0] = spA;
    g_snrow[bj * NROWS + i0] = snA;
    g_srow [bj * NROWS + i1] = spB;
    g_snrow[bj * NROWS + i1] = snB;

    if (!diag) {
        __syncthreads();
        // Merge 2 warps x 4 residues per column (fixed order), transposed slot.
        #pragma unroll
        for (int h = 0; h < 2; h++) {
            int c = tid + h * TB;
            unsigned long long pv =
                fadd2(fadd2(fadd2(cpn[0][c][0], cpn[0][c][1]),
                            fadd2(cpn[0][c][2], cpn[0][c][3])),
                      fadd2(fadd2(cpn[1][c][0], cpn[1][c][1]),
                            fadd2(cpn[1][c][2], cpn[1][c][3])));
            float csp, csn;
            asm("mov.b64 {%0, %1}, %2;" : "=f"(csp), "=f"(csn) : "l"(pv));
            int j = J0 + c;
            g_srow [bi * NROWS + j] = csp;
            g_snrow[bi * NROWS + j] = csn;
        }
    }
}

__global__ void ecstfl_cntzero_kernel() {
    if (threadIdx.x < NCLS) g_cnt[threadIdx.x] = 0;
}

__global__ void ecstfl_count_kernel(const int* __restrict__ lab) {
    int t = blockIdx.x * blockDim.x + threadIdx.x;
    if (t < NROWS) atomicAdd(&g_cnt[lab[t]], 1);   // int atomics: order-invariant
}

// Position-3 filler (also zeroes g_part) so main lands at captured slot 4.
__global__ void ecstfl_partzero_kernel() {
    if (threadIdx.x < FBLOCKS) g_part[threadIdx.x] = 0.0f;
}

// Finalize stage 1: 64 blocks x 128 threads; [slot][row] layout -> coalesced.
__global__ void __launch_bounds__(128)
ecstfl_final1_kernel(const int* __restrict__ lab) {
    __shared__ float red[128];
    const int i = blockIdx.x * 128 + threadIdx.x;

    float sp = 0.0f, sn = 0.0f;
    #pragma unroll
    for (int c = 0; c < NB; c++) {             // fixed order -> deterministic
        sp += g_srow [c * NROWS + i];
        sn += g_snrow[c * NROWS + i];
    }
    float cp  = (float)g_cnt[lab[i]];          // same-label count incl. self
    float att = sp / (cp + EPSV);              // (cnt-1)+1+eps == cnt+eps
    float rep = sn / ((float)NROWS - cp + 1.0f + EPSV);
    red[threadIdx.x] = att * rep;
    __syncthreads();
    #pragma unroll
    for (int o = 64; o > 0; o >>= 1) {
        if (threadIdx.x < o) red[threadIdx.x] += red[threadIdx.x + o];
        __syncthreads();
    }
    if (threadIdx.x == 0) g_part[blockIdx.x] = red[0];
}

__global__ void ecstfl_final2_kernel(float* __restrict__ out) {
    __shared__ float red[FBLOCKS];
    red[threadIdx.x] = g_part[threadIdx.x];
    __syncthreads();
    #pragma unroll
    for (int o = FBLOCKS / 2; o > 0; o >>= 1) {
        if (threadIdx.x < o) red[threadIdx.x] += red[threadIdx.x + o];
        __syncthreads();
    }
    if (threadIdx.x == 0)
        out[0] = red[0] / ((float)NROWS * (float)NROWS);   // mean(att*rep/N)
}

extern "C" void kernel_launch(void* const* d_in, const int* in_sizes, int n_in,
                              void* d_out, int out_size) {
    (void)in_sizes; (void)n_in; (void)out_size;
    const float* X   = (const float*)d_in[0];
    const int*   lab = (const int*)d_in[1];
    float* out = (float*)d_out;

    ecstfl_cntzero_kernel<<<1, 128>>>();                       // pos 1
    ecstfl_count_kernel<<<(NROWS + 255) / 256, 256>>>(lab);    // pos 2
    ecstfl_partzero_kernel<<<1, 64>>>();                       // pos 3 (filler)
    ecstfl_main_kernel<<<NTILES, TB>>>(X, lab);                // pos 4 <- profiled
    ecstfl_final1_kernel<<<FBLOCKS, 128>>>(lab);               // pos 5
    ecstfl_final2_kernel<<<1, FBLOCKS>>>(out);                 // pos 6
}

// round 10
// speedup vs baseline: 1.1862x; 1.0422x over previous
#include <cuda_runtime.h>
#include <cuda_bf16.h>
#include <cstdint>
#include <cmath>

#define NROWS 8192
#define DDIM  64
#define NCLS  100
#define EPSV  1e-6f

#define TB   64                 // threads per block (2 warps), 2 rows/thread
#define TILE 128                // tile edge: 128 i-rows x 128 j-rows
#define NB   (NROWS / TILE)     // 64 row-blocks
#define NTILES (NB * (NB + 1) / 2)   // 2080 upper-tri tiles
#define FBLOCKS 64

// Scratch (device globals; no allocation allowed).
// Layout [slot][row]: coalesced STG from main, coalesced LDG in final1.
// Every slot has exactly ONE writer per replay -> deterministic, no atomics.
__device__ float g_srow [NB * NROWS];
__device__ float g_snrow[NB * NROWS];
__device__ int   g_cnt[NCLS];
__device__ float g_part[FBLOCKS];

static __device__ __forceinline__ unsigned long long fadd2(unsigned long long a,
                                                           unsigned long long b) {
    unsigned long long r;
    asm("add.rn.f32x2 %0, %1, %2;" : "=l"(r) : "l"(a), "l"(b));
    return r;
}

static __device__ __forceinline__ float frcp(float x) {
    float r;
    asm("rcp.approx.f32 %0, %1;" : "=f"(r) : "f"(x));
    return r;
}

__global__ void __launch_bounds__(TB, 5)
ecstfl_main_kernel(const float* __restrict__ X, const int* __restrict__ lab) {
    __shared__ float shx[TILE * DDIM];              // -x_j/2 tile (32 KB)
    __shared__ int   shl[TILE];
    // Truncated-butterfly partials: [warp][jl][residue 0..3], packed (sp,sn).
    __shared__ unsigned long long cpn[2][TILE][4];  // 8 KB

    // Decode upper-triangular tile (bi <= bj) from linear block index.
    const int t = blockIdx.x;
    int bi = (int)(64.5f - sqrtf(64.5f * 64.5f - 2.0f * (float)t));
    while (bi > 0 && bi * NB - bi * (bi - 1) / 2 > t) bi--;
    while ((bi + 1) * NB - (bi + 1) * bi / 2 <= t) bi++;
    const int bj = bi + (t - (bi * NB - bi * (bi - 1) / 2));
    const bool diag = (bi == bj);

    const int tid  = threadIdx.x;
    const int w    = tid >> 5;
    const int lane = tid & 31;
    const int i0   = bi * TILE + tid;      // first owned row
    const int i1   = i0 + TB;              // second owned row
    const int J0   = bj * TILE;

    // Two rows of x_i in registers (raw scale).
    float xiA[DDIM], xiB[DDIM];
    {
        const float4* ra = (const float4*)(X + (size_t)i0 * DDIM);
        const float4* rb = (const float4*)(X + (size_t)i1 * DDIM);
        #pragma unroll
        for (int q = 0; q < DDIM / 4; q++) {
            float4 va = ra[q];
            xiA[4*q] = va.x; xiA[4*q+1] = va.y; xiA[4*q+2] = va.z; xiA[4*q+3] = va.w;
            float4 vb = rb[q];
            xiB[4*q] = vb.x; xiB[4*q+1] = vb.y; xiB[4*q+2] = vb.z; xiB[4*q+3] = vb.w;
        }
    }
    const int lA = lab[i0];
    const int lB = lab[i1];

    // Stage J tile as -x_j/2 (power-of-2 exact): 32 float4 per thread.
    {
        const float4* src = (const float4*)(X + (size_t)J0 * DDIM);
        float4* dst = (float4*)shx;
        #pragma unroll
        for (int r = 0; r < (TILE * DDIM / 4) / TB; r++) {
            float4 v = src[tid + r * TB];
            v.x *= -0.5f; v.y *= -0.5f; v.z *= -0.5f; v.w *= -0.5f;
            dst[tid + r * TB] = v;
        }
        shl[tid]      = lab[J0 + tid];
        shl[tid + TB] = lab[J0 + tid + TB];
    }
    __syncthreads();

    float spA = 0.0f, snA = 0.0f, spB = 0.0f, snB = 0.0f;

    // Process 4 j-rows per iteration: 2i x 4j register tile.
    #pragma unroll 1
    for (int jl = 0; jl < TILE; jl += 4) {
        const float4* row0 = (const float4*)(shx + (jl + 0) * DDIM);
        const float4* row1 = (const float4*)(shx + (jl + 1) * DDIM);
        const float4* row2 = (const float4*)(shx + (jl + 2) * DDIM);
        const float4* row3 = (const float4*)(shx + (jl + 3) * DDIM);
        // 16 FFMA-imm accumulator chains (2 i-rows x 4 j-rows x 2 halves).
        float aA00 = 0.0f, aA01 = 0.0f, aB00 = 0.0f, aB01 = 0.0f;  // j0
        float aA10 = 0.0f, aA11 = 0.0f, aB10 = 0.0f, aB11 = 0.0f;  // j1
        float aA20 = 0.0f, aA21 = 0.0f, aB20 = 0.0f, aB21 = 0.0f;  // j2
        float aA30 = 0.0f, aA31 = 0.0f, aB30 = 0.0f, aB31 = 0.0f;  // j3
        #pragma unroll
        for (int q = 0; q < 16; q++) {
            float xA0 = xiA[4*q+0], xA1 = xiA[4*q+1];
            float xA2 = xiA[4*q+2], xA3 = xiA[4*q+3];
            float xB0 = xiB[4*q+0], xB1 = xiB[4*q+1];
            float xB2 = xiB[4*q+2], xB3 = xiB[4*q+3];
            // j0/j1 pass (v regs reused afterwards for j2/j3)
            {
                float4 v0 = row0[q];                // LDS.128 broadcast
                float4 v1 = row1[q];
                float d0, d1, d2, d3;
                d0 = fmaf(xA0, 0.5f, v0.x);  d1 = fmaf(xA1, 0.5f, v0.y);
                d2 = fmaf(xB0, 0.5f, v0.x);  d3 = fmaf(xB1, 0.5f, v0.y);
                aA00 = fmaf(fabsf(d0), 2.0f, aA00);
                aA01 = fmaf(fabsf(d1), 2.0f, aA01);
                aB00 = fmaf(fabsf(d2), 2.0f, aB00);
                aB01 = fmaf(fabsf(d3), 2.0f, aB01);
                d0 = fmaf(xA2, 0.5f, v0.z);  d1 = fmaf(xA3, 0.5f, v0.w);
                d2 = fmaf(xB2, 0.5f, v0.z);  d3 = fmaf(xB3, 0.5f, v0.w);
                aA00 = fmaf(fabsf(d0), 2.0f, aA00);
                aA01 = fmaf(fabsf(d1), 2.0f, aA01);
                aB00 = fmaf(fabsf(d2), 2.0f, aB00);
                aB01 = fmaf(fabsf(d3), 2.0f, aB01);
                d0 = fmaf(xA0, 0.5f, v1.x);  d1 = fmaf(xA1, 0.5f, v1.y);
                d2 = fmaf(xB0, 0.5f, v1.x);  d3 = fmaf(xB1, 0.5f, v1.y);
                aA10 = fmaf(fabsf(d0), 2.0f, aA10);
                aA11 = fmaf(fabsf(d1), 2.0f, aA11);
                aB10 = fmaf(fabsf(d2), 2.0f, aB10);
                aB11 = fmaf(fabsf(d3), 2.0f, aB11);
                d0 = fmaf(xA2, 0.5f, v1.z);  d1 = fmaf(xA3, 0.5f, v1.w);
                d2 = fmaf(xB2, 0.5f, v1.z);  d3 = fmaf(xB3, 0.5f, v1.w);
                aA10 = fmaf(fabsf(d0), 2.0f, aA10);
                aA11 = fmaf(fabsf(d1), 2.0f, aA11);
                aB10 = fmaf(fabsf(d2), 2.0f, aB10);
                aB11 = fmaf(fabsf(d3), 2.0f, aB11);
            }
            // j2/j3 pass
            {
                float4 v2 = row2[q];
                float4 v3 = row3[q];
                float d0, d1, d2, d3;
                d0 = fmaf(xA0, 0.5f, v2.x);  d1 = fmaf(xA1, 0.5f, v2.y);
                d2 = fmaf(xB0, 0.5f, v2.x);  d3 = fmaf(xB1, 0.5f, v2.y);
                aA20 = fmaf(fabsf(d0), 2.0f, aA20);
                aA21 = fmaf(fabsf(d1), 2.0f, aA21);
                aB20 = fmaf(fabsf(d2), 2.0f, aB20);
                aB21 = fmaf(fabsf(d3), 2.0f, aB21);
                d0 = fmaf(xA2, 0.5f, v2.z);  d1 = fmaf(xA3, 0.5f, v2.w);
                d2 = fmaf(xB2, 0.5f, v2.z);  d3 = fmaf(xB3, 0.5f, v2.w);
                aA20 = fmaf(fabsf(d0), 2.0f, aA20);
                aA21 = fmaf(fabsf(d1), 2.0f, aA21);
                aB20 = fmaf(fabsf(d2), 2.0f, aB20);
                aB21 = fmaf(fabsf(d3), 2.0f, aB21);
                d0 = fmaf(xA0, 0.5f, v3.x);  d1 = fmaf(xA1, 0.5f, v3.y);
                d2 = fmaf(xB0, 0.5f, v3.x);  d3 = fmaf(xB1, 0.5f, v3.y);
                aA30 = fmaf(fabsf(d0), 2.0f, aA30);
                aA31 = fmaf(fabsf(d1), 2.0f, aA31);
                aB30 = fmaf(fabsf(d2), 2.0f, aB30);
                aB31 = fmaf(fabsf(d3), 2.0f, aB31);
                d0 = fmaf(xA2, 0.5f, v3.z);  d1 = fmaf(xA3, 0.5f, v3.w);
                d2 = fmaf(xB2, 0.5f, v3.z);  d3 = fmaf(xB3, 0.5f, v3.w);
                aA30 = fmaf(fabsf(d0), 2.0f, aA30);
                aA31 = fmaf(fabsf(d1), 2.0f, aA31);
                aB30 = fmaf(fabsf(d2), 2.0f, aB30);
                aB31 = fmaf(fabsf(d3), 2.0f, aB31);
            }
        }
        float dA0 = aA00 + aA01,  dB0 = aB00 + aB01;
        float dA1 = aA10 + aA11,  dB1 = aB10 + aB11;
        float dA2 = aA20 + aA21,  dB2 = aB20 + aB21;
        float dA3 = aA30 + aA31,  dB3 = aB30 + aB31;

        // Four independent epilogue chains, latencies mutually overlapped.
        float rA0 = frcp(dA0 + EPSV), rB0 = frcp(dB0 + EPSV);
        float rA1 = frcp(dA1 + EPSV), rB1 = frcp(dB1 + EPSV);
        float rA2 = frcp(dA2 + EPSV), rB2 = frcp(dB2 + EPSV);
        float rA3 = frcp(dA3 + EPSV), rB3 = frcp(dB3 + EPSV);
        int jb0 = shl[jl+0], jb1 = shl[jl+1], jb2 = shl[jl+2], jb3 = shl[jl+3];
        bool mA0 = (jb0 == lA), mB0 = (jb0 == lB);
        bool mA1 = (jb1 == lA), mB1 = (jb1 == lB);
        bool mA2 = (jb2 == lA), mB2 = (jb2 == lB);
        bool mA3 = (jb3 == lA), mB3 = (jb3 == lB);
        float cspA0 = mA0 ? dA0 : 0.0f,  csnA0 = mA0 ? 0.0f : rA0;
        float cspB0 = mB0 ? dB0 : 0.0f,  csnB0 = mB0 ? 0.0f : rB0;
        float cspA1 = mA1 ? dA1 : 0.0f,  csnA1 = mA1 ? 0.0f : rA1;
        float cspB1 = mB1 ? dB1 : 0.0f,  csnB1 = mB1 ? 0.0f : rB1;
        float cspA2 = mA2 ? dA2 : 0.0f,  csnA2 = mA2 ? 0.0f : rA2;
        float cspB2 = mB2 ? dB2 : 0.0f,  csnB2 = mB2 ? 0.0f : rB2;
        float cspA3 = mA3 ? dA3 : 0.0f,  csnA3 = mA3 ? 0.0f : rA3;
        float cspB3 = mB3 ? dB3 : 0.0f,  csnB3 = mB3 ? 0.0f : rB3;
        spA += (cspA0 + cspA1) + (cspA2 + cspA3);
        snA += (csnA0 + csnA1) + (csnA2 + csnA3);
        spB += (cspB0 + cspB1) + (cspB2 + cspB3);
        snB += (csnB0 + csnB1) + (csnB2 + csnB3);

        if (!diag) {
            // Four truncated butterflies (3 steps each), overlapped.
            unsigned long long pv0, pv1, pv2, pv3;
            {
                float s0 = cspA0 + cspB0, n0 = csnA0 + csnB0;
                float s1 = cspA1 + cspB1, n1 = csnA1 + csnB1;
                float s2 = cspA2 + cspB2, n2 = csnA2 + csnB2;
                float s3 = cspA3 + cspB3, n3 = csnA3 + csnB3;
                asm("mov.b64 %0, {%1, %2};" : "=l"(pv0) : "f"(s0), "f"(n0));
                asm("mov.b64 %0, {%1, %2};" : "=l"(pv1) : "f"(s1), "f"(n1));
                asm("mov.b64 %0, {%1, %2};" : "=l"(pv2) : "f"(s2), "f"(n2));
                asm("mov.b64 %0, {%1, %2};" : "=l"(pv3) : "f"(s3), "f"(n3));
            }
            #pragma unroll
            for (int o = 16; o >= 4; o >>= 1) {
                unsigned long long q0 = __shfl_xor_sync(0xFFFFFFFFu, pv0, o);
                unsigned long long q1 = __shfl_xor_sync(0xFFFFFFFFu, pv1, o);
                unsigned long long q2 = __shfl_xor_sync(0xFFFFFFFFu, pv2, o);
                unsigned long long q3 = __shfl_xor_sync(0xFFFFFFFFu, pv3, o);
                pv0 = fadd2(pv0, q0);
                pv1 = fadd2(pv1, q1);
                pv2 = fadd2(pv2, q2);
                pv3 = fadd2(pv3, q3);
            }
            if (lane < 4) {
                cpn[w][jl + 0][lane] = pv0;
                cpn[w][jl + 1][lane] = pv1;
                cpn[w][jl + 2][lane] = pv2;
                cpn[w][jl + 3][lane] = pv3;
            }
        }
    }

    // Row parts: unique slots [bj][i0], [bj][i1] (coalesced STG).
    g_srow [bj * NROWS + i0] = spA;
    g_snrow[bj * NROWS + i0] = snA;
    g_srow [bj * NROWS + i1] = spB;
    g_snrow[bj * NROWS + i1] = snB;

    if (!diag) {
        __syncthreads();
        // Merge 2 warps x 4 residues per column (fixed order), transposed slot.
        #pragma unroll
        for (int h = 0; h < 2; h++) {
            int c = tid + h * TB;
            unsigned long long pv =
                fadd2(fadd2(fadd2(cpn[0][c][0], cpn[0][c][1]),
                            fadd2(cpn[0][c][2], cpn[0][c][3])),
                      fadd2(fadd2(cpn[1][c][0], cpn[1][c][1]),
                            fadd2(cpn[1][c][2], cpn[1][c][3])));
            float csp, csn;
            asm("mov.b64 {%0, %1}, %2;" : "=f"(csp), "=f"(csn) : "l"(pv));
            int j = J0 + c;
            g_srow [bi * NROWS + j] = csp;
            g_snrow[bi * NROWS + j] = csn;
        }
    }
}

__global__ void ecstfl_cntzero_kernel() {
    if (threadIdx.x < NCLS) g_cnt[threadIdx.x] = 0;
}

__global__ void ecstfl_count_kernel(const int* __restrict__ lab) {
    int t = blockIdx.x * blockDim.x + threadIdx.x;
    if (t < NROWS) atomicAdd(&g_cnt[lab[t]], 1);   // int atomics: order-invariant
}

// Position-3 filler (also zeroes g_part) so main lands at captured slot 4.
__global__ void ecstfl_partzero_kernel() {
    if (threadIdx.x < FBLOCKS) g_part[threadIdx.x] = 0.0f;
}

// Finalize stage 1: 64 blocks x 128 threads; [slot][row] layout -> coalesced.
__global__ void __launch_bounds__(128)
ecstfl_final1_kernel(const int* __restrict__ lab) {
    __shared__ float red[128];
    const int i = blockIdx.x * 128 + threadIdx.x;

    float sp = 0.0f, sn = 0.0f;
    #pragma unroll
    for (int c = 0; c < NB; c++) {             // fixed order -> deterministic
        sp += g_srow [c * NROWS + i];
        sn += g_snrow[c * NROWS + i];
    }
    float cp  = (float)g_cnt[lab[i]];          // same-label count incl. self
    float att = sp / (cp + EPSV);              // (cnt-1)+1+eps == cnt+eps
    float rep = sn / ((float)NROWS - cp + 1.0f + EPSV);
    red[threadIdx.x] = att * rep;
    __syncthreads();
    #pragma unroll
    for (int o = 64; o > 0; o >>= 1) {
        if (threadIdx.x < o) red[threadIdx.x] += red[threadIdx.x + o];
        __syncthreads();
    }
    if (threadIdx.x == 0) g_part[blockIdx.x] = red[0];
}

__global__ void ecstfl_final2_kernel(float* __restrict__ out) {
    __shared__ float red[FBLOCKS];
    red[threadIdx.x] = g_part[threadIdx.x];
    __syncthreads();
    #pragma unroll
    for (int o = FBLOCKS / 2; o > 0; o >>= 1) {
        if (threadIdx.x < o) red[threadIdx.x] += red[threadIdx.x + o];
        __syncthreads();
    }
    if (threadIdx.x == 0)
        out[0] = red[0] / ((float)NROWS * (float)NROWS);   // mean(att*rep/N)
}

extern "C" void kernel_launch(void* const* d_in, const int* in_sizes, int n_in,
                              void* d_out, int out_size) {
    (void)in_sizes; (void)n_in; (void)out_size;
    const float* X   = (const float*)d_in[0];
    const int*   lab = (const int*)d_in[1];
    float* out = (float*)d_out;

    ecstfl_cntzero_kernel<<<1, 128>>>();                       // pos 1
    ecstfl_count_kernel<<<(NROWS + 255) / 256, 256>>>(lab);    // pos 2
    ecstfl_partzero_kernel<<<1, 64>>>();                       // pos 3 (filler)
    ecstfl_main_kernel<<<NTILES, TB>>>(X, lab);                // pos 4 <- profiled
    ecstfl_final1_kernel<<<FBLOCKS, 128>>>(lab);               // pos 5
    ecstfl_final2_kernel<<<1, FBLOCKS>>>(out);                 // pos 6
}